// round 1
// baseline (speedup 1.0000x reference)
#include <cuda_runtime.h>

#define NBOX 4096
#define T 1024
#define PER 4            // boxes per thread (NBOX / T)
#define NWARP (T / 32)
#define THRESH 0.05f
// sigma = 0.5  ->  exp(-(iou^2)/sigma) = exp(-2 * iou^2)
#define NEG_INV_SIGMA (-2.0f)

__global__ __launch_bounds__(T, 1)
void softnms_kernel(const float4* __restrict__ boxes,
                    const float*  __restrict__ scores,
                    float* __restrict__ out, int out_size)
{
    __shared__ unsigned long long swarp[NWARP];
    __shared__ unsigned long long ssel;

    const int t    = threadIdx.x;
    const int lane = t & 31;
    const int wid  = t >> 5;

    // ---- load my 4 boxes into registers ----
    float x1[PER], y1[PER], x2[PER], y2[PER], area[PER], s[PER], fin[PER];
    bool  proc[PER];
#pragma unroll
    for (int k = 0; k < PER; k++) {
        const int gi = t * PER + k;
        const float4 b = boxes[gi];
        x1[k] = b.x; y1[k] = b.y; x2[k] = b.z; y2[k] = b.w;
        area[k] = (b.z - b.x) * (b.w - b.y);
        s[k]    = scores[gi];
        fin[k]  = 0.0f;
        proc[k] = false;
    }

    int frozen_i = 0;
    int step = 0;
    for (; step < NBOX; step++) {
        // ---- local argmax over my unprocessed boxes ----
        // key = score_bits (scores always > 0) in high 32, (N-1-idx) low 32
        // -> max key == max score, ties broken toward LOWEST index (matches jnp.argmax)
        unsigned long long best = 0ull;
#pragma unroll
        for (int k = 0; k < PER; k++) {
            if (!proc[k]) {
                unsigned long long key =
                    ((unsigned long long)__float_as_uint(s[k]) << 32)
                    | (unsigned)(NBOX - 1 - (t * PER + k));
                if (key > best) best = key;
            }
        }
        // ---- warp reduce ----
#pragma unroll
        for (int o = 16; o > 0; o >>= 1) {
            unsigned long long v = __shfl_down_sync(0xffffffffu, best, o);
            if (v > best) best = v;
        }
        if (lane == 0) swarp[wid] = best;
        __syncthreads();
        // ---- block reduce in warp 0 ----
        if (wid == 0) {
            unsigned long long v = swarp[lane];
#pragma unroll
            for (int o = 16; o > 0; o >>= 1) {
                unsigned long long u = __shfl_down_sync(0xffffffffu, v, o);
                if (u > v) v = u;
            }
            if (lane == 0) ssel = v;
        }
        __syncthreads();

        const unsigned long long sk = ssel;
        const float sel = __uint_as_float((unsigned)(sk >> 32));
        const int   i   = NBOX - 1 - (int)(sk & 0xffffffffu);

        // idxs output is recorded for EVERY step (valid or not)
        if (t == 0 && (NBOX + step) < out_size) out[NBOX + step] = (float)i;

        if (!(sel > THRESH)) {
            // state is frozen from here on: every remaining step picks the
            // same argmax with zero score contribution -> early exit
            frozen_i = i;
            break;
        }

        // ---- decay all unprocessed boxes against selected box i ----
        const float4 b  = boxes[i];                 // same-address L1 broadcast
        const float  ai = (b.z - b.x) * (b.w - b.y);
#pragma unroll
        for (int k = 0; k < PER; k++) {
            if (proc[k]) continue;
            const int gi = t * PER + k;
            if (gi == i) {
                proc[k] = true;      // selected: score kept, marked processed
                fin[k]  = sel;       // selection-time score -> final output
            } else {
                const float xx1 = fmaxf(b.x, x1[k]);
                const float yy1 = fmaxf(b.y, y1[k]);
                const float xx2 = fminf(b.z, x2[k]);
                const float yy2 = fminf(b.w, y2[k]);
                const float iw  = fmaxf(xx2 - xx1, 0.0f);
                const float ih  = fmaxf(yy2 - yy1, 0.0f);
                const float inter = iw * ih;
                if (inter > 0.0f) {                  // ~95% of lanes skip exp/div
                    const float iou = inter / (ai + area[k] - inter);
                    s[k] *= expf(NEG_INV_SIGMA * iou * iou);
                }
            }
        }
        // no third barrier needed: the two barriers above already separate
        // this iteration's ssel/swarp reads from next iteration's writes
    }

    // ---- early-exit: fill remaining idxs with the frozen argmax ----
    if (step < NBOX) {
        for (int j = step + 1 + t; j < NBOX; j += T) {
            if ((NBOX + j) < out_size) out[NBOX + j] = (float)frozen_i;
        }
    }

    // ---- final scores ----
#pragma unroll
    for (int k = 0; k < PER; k++) {
        const int gi = t * PER + k;
        if (gi < out_size) out[gi] = fin[k];
    }
}

extern "C" void kernel_launch(void* const* d_in, const int* in_sizes, int n_in,
                              void* d_out, int out_size)
{
    // boxes has 4*NBOX elements, scores has NBOX — disambiguate by size
    const void* p0 = d_in[0];
    const void* p1 = d_in[1];
    const float4* boxes;
    const float*  scores;
    if (in_sizes[0] == 4 * NBOX) {
        boxes  = (const float4*)p0;
        scores = (const float*)p1;
    } else {
        boxes  = (const float4*)p1;
        scores = (const float*)p0;
    }
    softnms_kernel<<<1, T>>>(boxes, scores, (float*)d_out, out_size);
}

// round 2
// speedup vs baseline: 1.2522x; 1.2522x over previous
#include <cuda_runtime.h>

#define NBOX 4096
#define T 1024
#define PER 4
#define THRESH 0.05f

// sorted boxes, broadcast-read every iteration (L1-resident, one line/iter)
__device__ float4 g_sbox[NBOX];

__global__ __launch_bounds__(T, 1)
void softnms_kernel(const float4* __restrict__ boxes,
                    const float*  __restrict__ scores,
                    float* __restrict__ out, int out_size)
{
    __shared__ float skey[NBOX];   // x1 sort keys (sorted ascending after sort)
    __shared__ int   sperm[NBOX];  // sorted-pos -> original index
    __shared__ uint2 swarp[T / 32];
    __shared__ uint2 ssel;

    const int t    = threadIdx.x;
    const int lane = t & 31;
    const int wid  = t >> 5;

    // ---- init: zero score outputs, stage sort keys ----
#pragma unroll
    for (int k = 0; k < PER; k++) {
        const int gi = t * PER + k;
        if (gi < out_size) out[gi] = 0.0f;
        skey[gi]  = boxes[gi].x;   // x1
        sperm[gi] = gi;
    }
    __syncthreads();

    // ---- bitonic sort (ascending by x1), 4096 elems ----
    for (int k = 2; k <= NBOX; k <<= 1) {
        for (int j = k >> 1; j > 0; j >>= 1) {
#pragma unroll
            for (int e = t; e < NBOX; e += T) {
                const int ixj = e ^ j;
                if (ixj > e) {
                    const float a = skey[e], c = skey[ixj];
                    const bool up = ((e & k) == 0);
                    if (up ? (a > c) : (a < c)) {
                        skey[e] = c; skey[ixj] = a;
                        const int tmp = sperm[e]; sperm[e] = sperm[ixj]; sperm[ixj] = tmp;
                    }
                }
            }
            __syncthreads();
        }
    }

    // ---- load my 4 sorted boxes into registers; publish sorted boxes ----
    float x1[PER], y1[PER], x2[PER], y2[PER], area[PER], s[PER];
    int   orig[PER];
    unsigned procm = 0;
    float myx2max = 0.0f;
#pragma unroll
    for (int k = 0; k < PER; k++) {
        const int pos = t * PER + k;
        const int o   = sperm[pos];
        orig[k] = o;
        const float4 b = boxes[o];
        x1[k] = b.x; y1[k] = b.y; x2[k] = b.z; y2[k] = b.w;
        area[k] = (b.z - b.x) * (b.w - b.y);
        s[k]    = scores[o];
        g_sbox[pos] = b;
        myx2max = fmaxf(myx2max, b.z);
    }
    // warp x-slab bounds (sorted ascending -> min x1 = first slot of warp)
    const float wx1lo = skey[wid * (PER * 32)];
    const float wx2hi = __uint_as_float(
        __reduce_max_sync(0xffffffffu, __float_as_uint(myx2max)));
    __syncthreads();   // g_sbox visible, sperm stable

    unsigned bestbits = 0, bestpos = 0;
    bool dirty = true;
    int  selpos = 0;
    int  step = 0;

    for (; step < NBOX; step++) {
        // ---- local argmax (cached unless my scores changed) ----
        if (dirty) {
            bestbits = 0; bestpos = 0;
#pragma unroll
            for (int k = 0; k < PER; k++) {
                if (!((procm >> k) & 1u)) {
                    const unsigned ub = __float_as_uint(s[k]);  // scores > 0
                    if (ub > bestbits) { bestbits = ub; bestpos = t * PER + k; }
                }
            }
            dirty = false;
        }
        // ---- warp argmax: REDUX + ballot ----
        {
            const unsigned m   = __reduce_max_sync(0xffffffffu, bestbits);
            const unsigned bal = __ballot_sync(0xffffffffu, bestbits == m);
            const int src      = __ffs(bal) - 1;
            const unsigned wp  = __shfl_sync(0xffffffffu, bestpos, src);
            if (lane == 0) swarp[wid] = make_uint2(m, wp);
        }
        __syncthreads();
        // ---- block argmax in warp 0 ----
        if (wid == 0) {
            const uint2 v      = swarp[lane];
            const unsigned m2  = __reduce_max_sync(0xffffffffu, v.x);
            const unsigned b2  = __ballot_sync(0xffffffffu, v.x == m2);
            const int s2       = __ffs(b2) - 1;
            const unsigned p2  = __shfl_sync(0xffffffffu, v.y, s2);
            if (lane == 0) ssel = make_uint2(m2, p2);
        }
        __syncthreads();

        const uint2 sv  = ssel;
        const float sel = __uint_as_float(sv.x);
        selpos = (int)sv.y;

        // record selected index (original numbering) — owner thread has it in regs
        if ((selpos >> 2) == t && (NBOX + step) < out_size)
            out[NBOX + step] = (float)orig[selpos & 3];

        if (!(sel > THRESH)) break;   // state frozen from here on

        const float4 b = g_sbox[selpos];   // L1 broadcast

        // ---- warp-level spatial skip (conservative: reject => inter==0) ----
        if (b.x <= wx2hi && b.z >= wx1lo) {
            const float ai = (b.z - b.x) * (b.w - b.y);
#pragma unroll
            for (int k = 0; k < PER; k++) {
                if ((procm >> k) & 1u) continue;
                const int pos = t * PER + k;
                if (pos == selpos) {
                    procm |= 1u << k;
                    if (orig[k] < out_size) out[orig[k]] = sel;  // selection-time score
                    dirty = true;
                } else {
                    const float xx1 = fmaxf(b.x, x1[k]);
                    const float yy1 = fmaxf(b.y, y1[k]);
                    const float xx2 = fminf(b.z, x2[k]);
                    const float yy2 = fminf(b.w, y2[k]);
                    const float iw  = fmaxf(xx2 - xx1, 0.0f);
                    const float ih  = fmaxf(yy2 - yy1, 0.0f);
                    const float inter = iw * ih;
                    if (inter > 0.0f) {
                        const float iou = __fdividef(inter, ai + area[k] - inter);
                        s[k] *= __expf(-2.0f * iou * iou);
                        dirty = true;
                    }
                }
            }
        }
    }

    // ---- early-exit: remaining steps all re-select the frozen argmax ----
    if (step < NBOX) {
        const int fo = sperm[selpos];      // original index of frozen argmax
        for (int j = step + 1 + t; j < NBOX; j += T) {
            if ((NBOX + j) < out_size) out[NBOX + j] = (float)fo;
        }
    }
}

extern "C" void kernel_launch(void* const* d_in, const int* in_sizes, int n_in,
                              void* d_out, int out_size)
{
    const float4* boxes;
    const float*  scores;
    if (in_sizes[0] == 4 * NBOX) {
        boxes  = (const float4*)d_in[0];
        scores = (const float*)d_in[1];
    } else {
        boxes  = (const float4*)d_in[1];
        scores = (const float*)d_in[0];
    }
    softnms_kernel<<<1, T>>>(boxes, scores, (float*)d_out, out_size);
}

// round 3
// speedup vs baseline: 1.3688x; 1.0932x over previous
#include <cuda_runtime.h>

#define NBOX 4096
#define T 1024
#define PER 4
#define NWARP (T / 32)
#define THRESH 0.05f

// x1-sorted boxes; per-iteration read is a single L1-resident line broadcast
__device__ float4 g_sbox[NBOX];

__global__ __launch_bounds__(T, 1)
void softnms_kernel(const float4* __restrict__ boxes,
                    const float*  __restrict__ scores,
                    float* __restrict__ out, int out_size)
{
    __shared__ float skey[NBOX];        // sort keys (x1), ascending after sort
    __shared__ int   sperm[NBOX];       // sorted-pos -> original index
    __shared__ uint2 swarp[2][NWARP];   // double-buffered per-warp argmax
    __shared__ int   slast;             // last selected original index

    const int t    = threadIdx.x;
    const int lane = t & 31;
    const int wid  = t >> 5;

    // ---- init: zero score outputs, stage sort keys ----
#pragma unroll
    for (int k = 0; k < PER; k++) {
        const int gi = t * PER + k;
        if (gi < out_size) out[gi] = 0.0f;
        skey[gi]  = boxes[gi].x;
        sperm[gi] = gi;
    }
    __syncthreads();

    // ---- bitonic sort by x1, ascending ----
    for (int k = 2; k <= NBOX; k <<= 1) {
        for (int j = k >> 1; j > 0; j >>= 1) {
#pragma unroll
            for (int e = t; e < NBOX; e += T) {
                const int ixj = e ^ j;
                if (ixj > e) {
                    const float a = skey[e], c = skey[ixj];
                    const bool up = ((e & k) == 0);
                    if (up ? (a > c) : (a < c)) {
                        skey[e] = c; skey[ixj] = a;
                        const int tmp = sperm[e]; sperm[e] = sperm[ixj]; sperm[ixj] = tmp;
                    }
                }
            }
            __syncthreads();
        }
    }

    // ---- load my 4 sorted boxes into registers; publish sorted boxes ----
    float x1[PER], y1[PER], x2[PER], y2[PER], area[PER], s[PER];
    int   orig[PER];
    unsigned procm = 0;
    float tx2hi = 0.0f;
#pragma unroll
    for (int k = 0; k < PER; k++) {
        const int pos = t * PER + k;
        const int o   = sperm[pos];
        orig[k] = o;
        const float4 b = boxes[o];
        x1[k] = b.x; y1[k] = b.y; x2[k] = b.z; y2[k] = b.w;
        area[k] = (b.z - b.x) * (b.w - b.y);
        s[k]    = scores[o];
        g_sbox[pos] = b;
        tx2hi = fmaxf(tx2hi, b.z);
    }
    const float tx1lo = x1[0];   // slab sorted ascending -> min x1 is first
    __syncthreads();             // g_sbox + sort arrays settled (block-scope fence)

    unsigned cm = 0, cwp = 0;    // cached warp-level (maxbits, pos)
    bool dirty = true;
    int  step  = 0;

    for (; step < NBOX; step++) {
        // ---- warp argmax: recompute only if any lane's scores changed ----
        if (__ballot_sync(0xffffffffu, dirty)) {
            unsigned bb = 0, bp = 0;
#pragma unroll
            for (int k = 0; k < PER; k++) {
                if (!((procm >> k) & 1u)) {
                    const unsigned ub = __float_as_uint(s[k]);   // scores > 0
                    if (ub > bb) { bb = ub; bp = t * PER + k; }
                }
            }
            const unsigned m   = __reduce_max_sync(0xffffffffu, bb);
            const unsigned bal = __ballot_sync(0xffffffffu, bb == m);
            cwp = __shfl_sync(0xffffffffu, bp, __ffs(bal) - 1);
            cm  = m;
            dirty = false;
        }
        if (lane == 0) swarp[step & 1][wid] = make_uint2(cm, cwp);
        __syncthreads();   // the ONLY barrier per iteration

        // ---- every warp redundantly does the 32-entry final reduce ----
        const uint2 v       = swarp[step & 1][lane];
        const unsigned m2   = __reduce_max_sync(0xffffffffu, v.x);
        const unsigned b2   = __ballot_sync(0xffffffffu, v.x == m2);
        const int selpos    = (int)__shfl_sync(0xffffffffu, v.y, __ffs(b2) - 1);
        const float sel     = __uint_as_float(m2);

        // owner records the selected index (original numbering)
        if ((selpos >> 2) == t) {
            const int o = orig[selpos & 3];
            if ((NBOX + step) < out_size) out[NBOX + step] = (float)o;
            slast = o;
        }

        if (!(sel > THRESH)) break;   // state frozen from here on

        const float4 b = g_sbox[selpos];   // L1 broadcast (same address)

        // ---- thread-level spatial skip (exact: reject => inter == 0).
        //      Owner thread passes trivially (its box intersects itself). ----
        if (b.x <= tx2hi && b.z >= tx1lo) {
            const float ai = (b.z - b.x) * (b.w - b.y);
#pragma unroll
            for (int k = 0; k < PER; k++) {
                if ((procm >> k) & 1u) continue;
                const int pos = t * PER + k;
                if (pos == selpos) {
                    procm |= 1u << k;
                    if (orig[k] < out_size) out[orig[k]] = sel;  // selection-time score
                    dirty = true;
                } else {
                    const float xx1 = fmaxf(b.x, x1[k]);
                    const float yy1 = fmaxf(b.y, y1[k]);
                    const float xx2 = fminf(b.z, x2[k]);
                    const float yy2 = fminf(b.w, y2[k]);
                    const float iw  = fmaxf(xx2 - xx1, 0.0f);
                    const float ih  = fmaxf(yy2 - yy1, 0.0f);
                    const float inter = iw * ih;
                    if (inter > 0.0f) {
                        const float iou = __fdividef(inter, ai + area[k] - inter);
                        s[k] *= __expf(-2.0f * iou * iou);
                        dirty = true;
                    }
                }
            }
        }
        // next iteration writes the other swarp buffer -> one barrier suffices
    }

    // ---- early-exit: all remaining steps re-select the frozen argmax ----
    __syncthreads();
    if (step < NBOX) {
        const int fo = slast;
        for (int j = step + 1 + t; j < NBOX; j += T) {
            if ((NBOX + j) < out_size) out[NBOX + j] = (float)fo;
        }
    }
}

extern "C" void kernel_launch(void* const* d_in, const int* in_sizes, int n_in,
                              void* d_out, int out_size)
{
    const float4* boxes;
    const float*  scores;
    if (in_sizes[0] == 4 * NBOX) {
        boxes  = (const float4*)d_in[0];
        scores = (const float*)d_in[1];
    } else {
        boxes  = (const float4*)d_in[1];
        scores = (const float*)d_in[0];
    }
    softnms_kernel<<<1, T>>>(boxes, scores, (float*)d_out, out_size);
}